// round 1
// baseline (speedup 1.0000x reference)
#include <cuda_runtime.h>
#include <cuda_bf16.h>

// PreprocessLayerTorch: MIC pairwise distances + shifts + element one-hot.
// Output layout (float32), matching reference return order, flattened:
//   [0, n*4)                      onehot (n, 4)
//   [n*4, n*4 + n*n)              dist_masked (n, n)
//   [n*4 + n*n, n*4 + n*n + 3nn)  shift (n, n, 3)

#define NMAX 8192
__device__ float g_fx[NMAX];
__device__ float g_fy[NMAX];
__device__ float g_fz[NMAX];

__global__ void onehot_kernel(const int* __restrict__ elems,
                              float* __restrict__ out, int n) {
    int idx = blockIdx.x * blockDim.x + threadIdx.x;
    if (idx >= n * 4) return;
    int i = idx >> 2;
    int t = idx & 3;
    // ATOM_TYPES = {1, 6, 7, 8}
    int types[4] = {1, 6, 7, 8};
    out[idx] = (elems[i] == types[t]) ? 1.0f : 0.0f;
}

__global__ void frac_kernel(const float* __restrict__ coord,
                            const float* __restrict__ cell, int n) {
    int i = blockIdx.x * blockDim.x + threadIdx.x;
    if (i >= n) return;

    float c00 = cell[0], c01 = cell[1], c02 = cell[2];
    float c10 = cell[3], c11 = cell[4], c12 = cell[5];
    float c20 = cell[6], c21 = cell[7], c22 = cell[8];

    float det = c00 * (c11 * c22 - c12 * c21)
              - c01 * (c10 * c22 - c12 * c20)
              + c02 * (c10 * c21 - c11 * c20);
    float id = 1.0f / det;

    float i00 =  (c11 * c22 - c12 * c21) * id;
    float i01 = -(c01 * c22 - c02 * c21) * id;
    float i02 =  (c01 * c12 - c02 * c11) * id;
    float i10 = -(c10 * c22 - c12 * c20) * id;
    float i11 =  (c00 * c22 - c02 * c20) * id;
    float i12 = -(c00 * c12 - c02 * c10) * id;
    float i20 =  (c10 * c21 - c11 * c20) * id;
    float i21 = -(c00 * c21 - c01 * c20) * id;
    float i22 =  (c00 * c11 - c01 * c10) * id;

    float x = coord[3 * i + 0];
    float y = coord[3 * i + 1];
    float z = coord[3 * i + 2];

    // frac = coord @ h_inv  (row vector times matrix)
    float fx = x * i00 + y * i10 + z * i20;
    float fy = x * i01 + y * i11 + z * i21;
    float fz = x * i02 + y * i12 + z * i22;

    fx -= floorf(fx);
    fy -= floorf(fy);
    fz -= floorf(fz);

    g_fx[i] = fx;
    g_fy[i] = fy;
    g_fz[i] = fz;
}

__global__ __launch_bounds__(128)
void pair_kernel(const float* __restrict__ cell,
                 float* __restrict__ dist_out,
                 float* __restrict__ shift_out, int n) {
    int i = blockIdx.y;
    int j0 = (blockIdx.x * blockDim.x + threadIdx.x) * 4;
    if (j0 >= n) return;

    float c00 = __ldg(cell + 0), c01 = __ldg(cell + 1), c02 = __ldg(cell + 2);
    float c10 = __ldg(cell + 3), c11 = __ldg(cell + 4), c12 = __ldg(cell + 5);
    float c20 = __ldg(cell + 6), c21 = __ldg(cell + 7), c22 = __ldg(cell + 8);

    float fxi = g_fx[i], fyi = g_fy[i], fzi = g_fz[i];

    // Vectorized loads of 4 consecutive j's (n % 4 == 0 for this problem;
    // guarded by launch geometry otherwise).
    float4 fxj = *reinterpret_cast<const float4*>(g_fx + j0);
    float4 fyj = *reinterpret_cast<const float4*>(g_fy + j0);
    float4 fzj = *reinterpret_cast<const float4*>(g_fz + j0);

    float fxs[4] = {fxj.x, fxj.y, fxj.z, fxj.w};
    float fys[4] = {fyj.x, fyj.y, fyj.z, fyj.w};
    float fzs[4] = {fzj.x, fzj.y, fzj.z, fzj.w};

    float dvals[4];
    float svals[12];

#pragma unroll
    for (int k = 0; k < 4; k++) {
        float dfx = fxs[k] - fxi;
        float dfy = fys[k] - fyi;
        float dfz = fzs[k] - fzi;

        // shift = -round(dfrac), round-half-to-even == jnp.round
        float sx = -rintf(dfx);
        float sy = -rintf(dfy);
        float sz = -rintf(dfz);
        dfx += sx;
        dfy += sy;
        dfz += sz;

        // d = dfrac @ cell
        float dx = dfx * c00 + dfy * c10 + dfz * c20;
        float dy = dfx * c01 + dfy * c11 + dfz * c21;
        float dz = dfx * c02 + dfy * c12 + dfz * c22;

        float d2 = dx * dx + dy * dy + dz * dz;
        bool m = (d2 > 0.0f) && (d2 < 25.0f);  // RC = 5.0
        dvals[k] = m ? sqrtf(d2) : 0.0f;

        svals[3 * k + 0] = sx;
        svals[3 * k + 1] = sy;
        svals[3 * k + 2] = sz;
    }

    long long base = (long long)i * n + j0;
    *reinterpret_cast<float4*>(dist_out + base) =
        make_float4(dvals[0], dvals[1], dvals[2], dvals[3]);

    float* sp = shift_out + base * 3;  // 16B-aligned: 3*j0*4 bytes, j0 % 4 == 0
    reinterpret_cast<float4*>(sp)[0] =
        make_float4(svals[0], svals[1], svals[2], svals[3]);
    reinterpret_cast<float4*>(sp)[1] =
        make_float4(svals[4], svals[5], svals[6], svals[7]);
    reinterpret_cast<float4*>(sp)[2] =
        make_float4(svals[8], svals[9], svals[10], svals[11]);
}

extern "C" void kernel_launch(void* const* d_in, const int* in_sizes, int n_in,
                              void* d_out, int out_size) {
    const float* coord = (const float*)d_in[0];   // (n, 3) float32
    const float* cell  = (const float*)d_in[1];   // (3, 3) float32
    const int*   elems = (const int*)d_in[2];     // (n,)   int32

    int n = in_sizes[0] / 3;

    float* out       = (float*)d_out;
    float* onehot    = out;                        // n*4
    float* dist_out  = out + (long long)n * 4;     // n*n
    float* shift_out = dist_out + (long long)n * n;// n*n*3

    // 1) one-hot
    {
        int total = n * 4;
        int threads = 256;
        int blocks = (total + threads - 1) / threads;
        onehot_kernel<<<blocks, threads>>>(elems, out, n);
    }

    // 2) fractional coords (wrapped)
    {
        int threads = 256;
        int blocks = (n + threads - 1) / threads;
        frac_kernel<<<blocks, threads>>>(coord, cell, n);
    }

    // 3) pairwise dist + shift
    {
        const int THREADS = 128;
        int jblocks = (n + THREADS * 4 - 1) / (THREADS * 4);
        dim3 grid(jblocks, n);
        pair_kernel<<<grid, THREADS>>>(cell, dist_out, shift_out, n);
    }
}